// round 13
// baseline (speedup 1.0000x reference)
#include <cuda_runtime.h>
#include <math_constants.h>

#define BB 64
#define NN 64
#define TT 100
#define CH 10                      // t-slices per block
#define NCHUNK (TT / CH)           // 10, exact
#define NTHR (CH * BB)             // 640

// Partials: [n][chunk][b] (160 KB, L2-resident). Ticket counters per n.
static __device__ float g_partial[NN * NCHUNK * BB];
static __device__ int   g_ctr[NN];          // zero-init at load; self-resetting

__global__ __launch_bounds__(NTHR) void social_fused_kernel(
    const float* __restrict__ x,
    const float* __restrict__ wfa,
    const int*   __restrict__ rand_idx,
    const int*   __restrict__ drop_mask,
    float*       __restrict__ out)
{
    const int n     = blockIdx.x;            // 0..63
    const int chunk = blockIdx.y;            // 0..9
    const int tid   = threadIdx.x;
    const int tsub  = tid >> 6;              // 0..9
    const int b     = tid & 63;              // 0..63
    const int lane  = tid & 31;
    const int base  = b & 32;                // b-half this warp owns
    const int t     = chunk * CH + tsub;     // < 100 always

    __shared__ float2 sx[BB][3 * CH];        // staged x (15.4 KB)
    __shared__ float4 s[CH][BB];             // 10 KB
    __shared__ float  red[CH][BB];           // 2.5 KB
    __shared__ int    winner;

    // Stage x cooperatively: row b needs 30 aligned float2 starting at
    // float2 index ((b*NN+n)*TT + chunk*CH)*3. Consecutive threads load
    // consecutive float2 within a row -> ~3 sectors/warp.
    const float2* x2 = (const float2*)x;
    #pragma unroll
    for (int i = tid; i < BB * 3 * CH; i += NTHR) {
        const int bb = i / (3 * CH);
        const int j  = i - bb * (3 * CH);
        sx[bb][j] = x2[((size_t)(bb * NN + n) * TT + chunk * CH) * 3 + j];
    }

    // Per-batch transform R, trans (L1-hot)
    const float* w = wfa + b * 9;
    const float r00 = w[0], r01 = w[1], tx = w[2];
    const float r10 = w[3], r11 = w[4], ty = w[5];

    // Control loads (coalesced in b)
    const int idx  = (t * NN + n) * BB + b;  // row = t*N + n, col = b
    const int ri   = rand_idx[idx];
    const int drop = drop_mask[idx];
    __syncthreads();

    // (px, py) at t-offset tsub*6 floats -> float2 index tsub*3
    const float2 p2 = sx[b][tsub * 3];

    const float gx = fmaf(r00, p2.x, r01 * p2.y) + tx;
    const float gy = fmaf(r10, p2.x, r11 * p2.y) + ty;
    const float sq = fmaf(gx, gx, gy * gy);

    s[tsub][b] = make_float4(gx, gy, sq, 0.0f);
    __syncthreads();

    // My two candidates (c = lane, c = lane+32), premultiplied by -2.
    const float4 caf = s[tsub][lane];
    const float4 cbf = s[tsub][lane + 32];
    const float ca2x = -2.0f * caf.x, ca2y = -2.0f * caf.y, caz = caf.z;
    const float cb2x = -2.0f * cbf.x, cb2y = -2.0f * cbf.y, cbz = cbf.z;

    // Compacted argmin (proven R10/R12): only drop==0 lanes (~20%) need it.
    // Packed key (key & ~63) | c, REDUX.MIN per needy target; low-bit index
    // breaks ties toward smaller c (jnp.argmin first-occurrence).
    unsigned int my_cmin = 0;
    const unsigned need = __ballot_sync(0xffffffffu, drop == 0);
    for (unsigned m = need; m; m &= m - 1u) {
        const int tb = __ffs(m) - 1;            // target lane
        const float4 tg = s[tsub][base | tb];   // broadcast LDS

        float k1 = fmaf(tg.x, ca2x, fmaf(tg.y, ca2y, caz)) + tg.z;
        float k2 = fmaf(tg.x, cb2x, fmaf(tg.y, cb2y, cbz)) + tg.z;
        k1 = fmaxf(k1, 1e-12f);
        k2 = fmaxf(k2, 1e-12f);
        unsigned uk1 = (__float_as_uint(k1) & 0xFFFFFFC0u) | (unsigned)lane;
        unsigned uk2 = (__float_as_uint(k2) & 0xFFFFFFC0u) | (unsigned)(lane + 32);

        // Diagonal: candidate c == target b sits at lane==tb, half = base.
        if (lane == tb) { if (base) uk2 = 0xFFFFFFFFu; else uk1 = 0xFFFFFFFFu; }

        const unsigned best = __reduce_min_sync(0xffffffffu, min(uk1, uk2));
        if (tb == lane) my_cmin = best & 63u;
    }

    const int rnb = ri + (ri >= b ? 1 : 0);
    const int nb  = drop ? rnb : (int)my_cmin;

    const float4 p  = s[tsub][nb];
    const float  d2 = (sq + p.z) - 2.0f * fmaf(gx, p.x, gy * p.y);
    const float  nd = sqrtf(fmaxf(d2, 1e-12f));
    const float  df = nd - 1.5f;

    red[tsub][b] = df * df;
    __syncthreads();

    if (tsub == 0) {
        float acc = 0.0f;
        #pragma unroll
        for (int j = 0; j < CH; ++j) acc += red[j][b];
        g_partial[(n * NCHUNK + chunk) * BB + b] = acc;   // coalesced in b
        __threadfence();                      // publish before ticket
    }
    __syncthreads();

    if (tid == 0) {
        const int old = atomicAdd(&g_ctr[n], 1);
        winner = (old == NCHUNK - 1);
    }
    __syncthreads();

    if (winner) {                             // last-arriving block for this n
        __threadfence();
        // 640 threads load the 10x64 partials (kq = chunk, rb = b), smem reduce
        const int rb = tid & 63;
        const int kq = tid >> 6;              // 0..9
        red[kq][rb] = g_partial[(n * NCHUNK + kq) * BB + rb];
        __syncthreads();
        if (kq == 0) {
            float tot = 0.0f;
            #pragma unroll
            for (int j = 0; j < NCHUNK; ++j) tot += red[j][rb];
            out[rb * NN + n] = tot * (1.0f / (float)TT);
            if (rb == 0) g_ctr[n] = 0;        // reset for next graph replay
        }
    }
}

extern "C" void kernel_launch(void* const* d_in, const int* in_sizes, int n_in,
                              void* d_out, int out_size)
{
    const float* x    = (const float*)d_in[0];
    const float* wfa  = (const float*)d_in[1];
    const int*   ridx = (const int*)d_in[2];
    const int*   mask = (const int*)d_in[3];
    float*       out  = (float*)d_out;

    dim3 grid(NN, NCHUNK);
    social_fused_kernel<<<grid, NTHR>>>(x, wfa, ridx, mask, out);
}

// round 14
// speedup vs baseline: 1.0086x; 1.0086x over previous
#include <cuda_runtime.h>
#include <math_constants.h>

#define BB 64
#define NN 64
#define TT 100
#define CH 13                      // t-slices per CTA
#define NCHUNK 8                   // CTAs per n == cluster size (8*13=104 >= 100)
#define NTHR (CH * BB)             // 832
#define XF2  (BB * NN * TT * 3)    // total float2 count in x (1,228,800)

__global__ __launch_bounds__(NTHR) __cluster_dims__(1, NCHUNK, 1)
void social_cluster_kernel(
    const float* __restrict__ x,
    const float* __restrict__ wfa,
    const int*   __restrict__ rand_idx,
    const int*   __restrict__ drop_mask,
    float*       __restrict__ out)
{
    const int n     = blockIdx.x;            // 0..63
    const int chunk = blockIdx.y;            // 0..7 == cluster rank
    const int tid   = threadIdx.x;
    const int tsub  = tid >> 6;              // 0..12
    const int b     = tid & 63;              // 0..63
    const int lane  = tid & 31;
    const int base  = b & 32;                // b-half this warp owns
    const int t     = chunk * CH + tsub;     // may exceed 99 -> masked
    const bool active = (t < TT);            // uniform per warp

    __shared__ float2 sx[BB][3 * CH];        // staged x (19.5 KB)
    __shared__ float4 s[CH][BB];             // 13 KB
    __shared__ float  red[CH][BB];           // 3.25 KB
    __shared__ float  cpart[NCHUNK][BB];     // cluster partials (rank 0 uses)

    // Stage x cooperatively: row b needs 3*CH aligned float2 starting at
    // float2 index ((b*NN+n)*TT + chunk*CH)*3. Clamp: last row of last chunk
    // would run 22 floats past the array end (values masked anyway).
    const float2* x2 = (const float2*)x;
    #pragma unroll
    for (int i = tid; i < BB * 3 * CH; i += NTHR) {
        const int bb = i / (3 * CH);
        const int j  = i - bb * (3 * CH);
        int gi = ((bb * NN + n) * TT + chunk * CH) * 3 + j;
        gi = min(gi, XF2 - 1);
        sx[bb][j] = x2[gi];
    }

    // Per-batch transform R, trans (L1-hot)
    const float* w = wfa + b * 9;
    const float r00 = w[0], r01 = w[1], tx = w[2];
    const float r10 = w[3], r11 = w[4], ty = w[5];

    // Control loads (coalesced in b); guard OOB for masked t
    int ri = 0, drop = 1;
    if (active) {
        const int idx = (t * NN + n) * BB + b;  // row = t*N + n, col = b
        ri   = rand_idx[idx];
        drop = drop_mask[idx];
    }
    __syncthreads();

    // (px, py) at t-offset tsub*6 floats -> float2 index tsub*3
    const float2 p2 = sx[b][tsub * 3];

    const float gx = fmaf(r00, p2.x, r01 * p2.y) + tx;
    const float gy = fmaf(r10, p2.x, r11 * p2.y) + ty;
    const float sq = fmaf(gx, gx, gy * gy);

    s[tsub][b] = make_float4(gx, gy, sq, 0.0f);
    __syncthreads();

    // My two candidates (c = lane, c = lane+32), premultiplied by -2.
    const float4 caf = s[tsub][lane];
    const float4 cbf = s[tsub][lane + 32];
    const float ca2x = -2.0f * caf.x, ca2y = -2.0f * caf.y, caz = caf.z;
    const float cb2x = -2.0f * cbf.x, cb2y = -2.0f * cbf.y, cbz = cbf.z;

    // Compacted argmin (proven R10/R12): only drop==0 lanes (~20%) need it.
    // Masked warps have drop==1 everywhere -> need==0 -> loop skipped.
    unsigned int my_cmin = 0;
    const unsigned need = __ballot_sync(0xffffffffu, drop == 0);
    for (unsigned m = need; m; m &= m - 1u) {
        const int tb = __ffs(m) - 1;            // target lane
        const float4 tg = s[tsub][base | tb];   // broadcast LDS

        float k1 = fmaf(tg.x, ca2x, fmaf(tg.y, ca2y, caz)) + tg.z;
        float k2 = fmaf(tg.x, cb2x, fmaf(tg.y, cb2y, cbz)) + tg.z;
        k1 = fmaxf(k1, 1e-12f);
        k2 = fmaxf(k2, 1e-12f);
        unsigned uk1 = (__float_as_uint(k1) & 0xFFFFFFC0u) | (unsigned)lane;
        unsigned uk2 = (__float_as_uint(k2) & 0xFFFFFFC0u) | (unsigned)(lane + 32);

        // Diagonal: candidate c == target b sits at lane==tb, half = base.
        if (lane == tb) { if (base) uk2 = 0xFFFFFFFFu; else uk1 = 0xFFFFFFFFu; }

        const unsigned best = __reduce_min_sync(0xffffffffu, min(uk1, uk2));
        if (tb == lane) my_cmin = best & 63u;
    }

    const int rnb = ri + (ri >= b ? 1 : 0);
    const int nb  = drop ? rnb : (int)my_cmin;

    const float4 p  = s[tsub][nb];
    const float  d2 = (sq + p.z) - 2.0f * fmaf(gx, p.x, gy * p.y);
    const float  nd = sqrtf(fmaxf(d2, 1e-12f));
    const float  df = nd - 1.5f;

    red[tsub][b] = active ? (df * df) : 0.0f;
    __syncthreads();

    // Per-CTA partial over its CH slices, sent to rank 0's cpart[chunk][b]
    if (tsub == 0) {
        float acc = 0.0f;
        #pragma unroll
        for (int j = 0; j < CH; ++j) acc += red[j][b];

        unsigned int lsm = (unsigned int)__cvta_generic_to_shared(&cpart[chunk][b]);
        unsigned int rem;
        asm volatile("mapa.shared::cluster.u32 %0, %1, %2;"
                     : "=r"(rem) : "r"(lsm), "r"(0));
        asm volatile("st.shared::cluster.f32 [%0], %1;"
                     :: "r"(rem), "f"(acc) : "memory");
    }

    // Cluster barrier: arrive releases the DSMEM stores; wait makes them
    // visible to rank 0.
    asm volatile("barrier.cluster.arrive.aligned;" ::: "memory");
    asm volatile("barrier.cluster.wait.aligned;" ::: "memory");

    if (chunk == 0 && tsub == 0) {
        float tot = 0.0f;
        #pragma unroll
        for (int r = 0; r < NCHUNK; ++r) tot += cpart[r][b];
        out[b * NN + n] = tot * (1.0f / (float)TT);
    }
}

extern "C" void kernel_launch(void* const* d_in, const int* in_sizes, int n_in,
                              void* d_out, int out_size)
{
    const float* x    = (const float*)d_in[0];
    const float* wfa  = (const float*)d_in[1];
    const int*   ridx = (const int*)d_in[2];
    const int*   mask = (const int*)d_in[3];
    float*       out  = (float*)d_out;

    dim3 grid(NN, NCHUNK);
    social_cluster_kernel<<<grid, NTHR>>>(x, wfa, ridx, mask, out);
}